// round 1
// baseline (speedup 1.0000x reference)
#include <cuda_runtime.h>
#include <math.h>

#define NN 20000
#define DD 256
#define HH 4
#define DHH 64
#define LL 2
#define EE 320000
#define KK 48
#define LN_EPS 1e-5f

// ---------------- scratch (static device globals; no allocation) -------------
__device__ float g_kall[LL][(size_t)NN * DD];
__device__ float g_vall[LL][(size_t)NN * DD];
__device__ float g_q[(size_t)NN * DD];
__device__ float g_x[(size_t)NN * DD];
__device__ float g_ao[(size_t)NN * DD];
__device__ float g_h[(size_t)NN * 2 * DD];
__device__ float g_t[(size_t)NN * DD];
__device__ int   g_counts[NN];
__device__ int   g_nbr[NN * KK];
__device__ int   g_pad[NN * KK];

// ---------------- neighbor build --------------------------------------------
__global__ void nbr_init_kernel() {
    int i = blockIdx.x * blockDim.x + threadIdx.x;
    if (i < NN) g_counts[i] = 0;
    if (i < NN * KK) g_pad[i] = 1;
}

__global__ void nbr_scatter_kernel(const int* __restrict__ ei) {
    int e = blockIdx.x * blockDim.x + threadIdx.x;
    if (e >= EE) return;
    int s = ei[e];
    int t = ei[EE + e];
    int p = atomicAdd(&g_counts[t], 1);
    if (p < KK) {
        g_nbr[t * KK + p] = s;
        g_pad[t * KK + p] = 0;
    }
}

__global__ void nbr_iso_kernel() {
    int n = blockIdx.x * blockDim.x + threadIdx.x;
    if (n < NN && g_counts[n] == 0) {
        g_nbr[n * KK] = n;
        g_pad[n * KK] = 0;
    }
}

// ---------------- GEMM: C[M,Nout] = A[M,Kd] @ B[Nout,Kd]^T + bias (+gelu) ----
// Tile 64x64, Kstep 32, 256 threads, 4x4 per-thread register tile.
__global__ void gemm_bias_kernel(const float* __restrict__ A,
                                 const float* __restrict__ B,
                                 const float* __restrict__ bias,
                                 float* __restrict__ C,
                                 int M, int Nout, int Kd, int act) {
    __shared__ float As[32][65];
    __shared__ float Bs[32][65];
    int tid = threadIdx.x;
    int tx = tid & 15;      // 0..15 -> n
    int ty = tid >> 4;      // 0..15 -> m
    int m0 = blockIdx.y * 64;
    int n0 = blockIdx.x * 64;

    float acc[4][4] = {};
    int c = tid & 31;       // k within tile
    int r0 = tid >> 5;      // 0..7

    for (int k0 = 0; k0 < Kd; k0 += 32) {
#pragma unroll
        for (int i = 0; i < 8; i++) {
            int r = r0 + i * 8;
            int m = m0 + r;
            As[c][r] = (m < M) ? A[(size_t)m * Kd + k0 + c] : 0.0f;
            Bs[c][r] = B[(size_t)(n0 + r) * Kd + k0 + c];
        }
        __syncthreads();
#pragma unroll
        for (int kk = 0; kk < 32; kk++) {
            float a[4], b[4];
#pragma unroll
            for (int i = 0; i < 4; i++) a[i] = As[kk][ty + 16 * i];
#pragma unroll
            for (int j = 0; j < 4; j++) b[j] = Bs[kk][tx + 16 * j];
#pragma unroll
            for (int i = 0; i < 4; i++)
#pragma unroll
                for (int j = 0; j < 4; j++) acc[i][j] += a[i] * b[j];
        }
        __syncthreads();
    }

#pragma unroll
    for (int i = 0; i < 4; i++) {
        int m = m0 + ty + 16 * i;
        if (m >= M) continue;
#pragma unroll
        for (int j = 0; j < 4; j++) {
            int n = n0 + tx + 16 * j;
            float v = acc[i][j] + bias[n];
            if (act) v = 0.5f * v * (1.0f + erff(v * 0.70710678118654752f));
            C[(size_t)m * Nout + n] = v;
        }
    }
}

// ---------------- attention: one block per node, one warp per head ----------
__global__ void attn_kernel(const float* __restrict__ q,
                            const float* __restrict__ kall,
                            const float* __restrict__ vall,
                            float* __restrict__ ao) {
    int n = blockIdx.x;
    int warp = threadIdx.x >> 5;   // head
    int lane = threadIdx.x & 31;

    __shared__ float s_sc[HH][KK];
    __shared__ int   s_nbr[KK];
    __shared__ int   s_pad[KK];

    for (int j = threadIdx.x; j < KK; j += blockDim.x) {
        s_nbr[j] = g_nbr[n * KK + j];
        s_pad[j] = g_pad[n * KK + j];
    }
    __syncthreads();

    const float2* q2 = (const float2*)(q + (size_t)n * DD + warp * DHH);
    float2 myq = q2[lane];

    // scores (warp-cooperative dot over DH=64: 2 floats per lane)
    for (int j = 0; j < KK; j++) {
        if (s_pad[j]) {
            if (lane == 0) s_sc[warp][j] = -1e30f;
            continue;
        }
        const float2* k2 = (const float2*)(kall + (size_t)s_nbr[j] * DD + warp * DHH);
        float2 kv = k2[lane];
        float dot = myq.x * kv.x + myq.y * kv.y;
#pragma unroll
        for (int o = 16; o; o >>= 1) dot += __shfl_xor_sync(0xffffffffu, dot, o);
        if (lane == 0) s_sc[warp][j] = dot * 0.125f;   // 1/sqrt(64)
    }
    __syncwarp();

    // softmax over K=48: lane handles j=lane and (lane<16) j=lane+32
    float a0 = s_sc[warp][lane];
    float a1 = (lane < 16) ? s_sc[warp][lane + 32] : -1e30f;
    float mx = fmaxf(a0, a1);
#pragma unroll
    for (int o = 16; o; o >>= 1) mx = fmaxf(mx, __shfl_xor_sync(0xffffffffu, mx, o));
    float e0 = __expf(a0 - mx);
    float e1 = (lane < 16) ? __expf(a1 - mx) : 0.0f;
    float s = e0 + e1;
#pragma unroll
    for (int o = 16; o; o >>= 1) s += __shfl_xor_sync(0xffffffffu, s, o);
    float inv = 1.0f / s;
    s_sc[warp][lane] = e0 * inv;
    if (lane < 16) s_sc[warp][lane + 32] = e1 * inv;
    __syncwarp();

    // weighted sum of V
    float2 acc = {0.0f, 0.0f};
    for (int j = 0; j < KK; j++) {
        if (s_pad[j]) continue;
        float w = s_sc[warp][j];
        const float2* v2 = (const float2*)(vall + (size_t)s_nbr[j] * DD + warp * DHH);
        float2 vv = v2[lane];
        acc.x += w * vv.x;
        acc.y += w * vv.y;
    }
    ((float2*)(ao + (size_t)n * DD + warp * DHH))[lane] = acc;
}

// ---------------- residual add + layernorm (one block of 256 per node) ------
__global__ void add_ln_kernel(const float* __restrict__ x,
                              const float* __restrict__ y,
                              const float* __restrict__ g,
                              const float* __restrict__ b,
                              float* __restrict__ out) {
    int n = blockIdx.x;
    int t = threadIdx.x;
    size_t idx = (size_t)n * DD + t;
    float v = x[idx] + y[idx];

    float s = v, s2 = v * v;
#pragma unroll
    for (int o = 16; o; o >>= 1) {
        s  += __shfl_xor_sync(0xffffffffu, s,  o);
        s2 += __shfl_xor_sync(0xffffffffu, s2, o);
    }
    __shared__ float rs[8], rs2[8];
    if ((t & 31) == 0) { rs[t >> 5] = s; rs2[t >> 5] = s2; }
    __syncthreads();
    float S = 0.0f, S2 = 0.0f;
#pragma unroll
    for (int i = 0; i < 8; i++) { S += rs[i]; S2 += rs2[i]; }
    float mu  = S * (1.0f / DD);
    float var = S2 * (1.0f / DD) - mu * mu;
    out[idx] = (v - mu) * rsqrtf(var + LN_EPS) * g[t] + b[t];
}

// ---------------- launch -----------------------------------------------------
static inline void run_gemm(const float* A, const float* B, const float* bias,
                            float* C, int M, int Nout, int Kd, int act) {
    dim3 grid(Nout / 64, (M + 63) / 64);
    gemm_bias_kernel<<<grid, 256>>>(A, B, bias, C, M, Nout, Kd, act);
}

extern "C" void kernel_launch(void* const* d_in, const int* in_sizes, int n_in,
                              void* d_out, int out_size) {
    const float* expr    = (const float*)d_in[0];
    const float* spatial = (const float*)d_in[1];
    const float* ipw     = (const float*)d_in[2];   // (L, 3D, D)
    const float* ipb     = (const float*)d_in[3];   // (L, 3D)
    const float* opw     = (const float*)d_in[4];   // (L, D, D)
    const float* opb     = (const float*)d_in[5];   // (L, D)
    const float* w1      = (const float*)d_in[6];   // (L, 2D, D)
    const float* b1      = (const float*)d_in[7];   // (L, 2D)
    const float* w2      = (const float*)d_in[8];   // (L, D, 2D)
    const float* b2      = (const float*)d_in[9];   // (L, D)
    const float* ln1g    = (const float*)d_in[10];
    const float* ln1b    = (const float*)d_in[11];
    const float* ln2g    = (const float*)d_in[12];
    const float* ln2b    = (const float*)d_in[13];
    const int*   ei      = (const int*)d_in[14];    // (2, E)
    float* out = (float*)d_out;

    float *kall, *vall, *q, *x, *ao, *h, *tmp;
    cudaGetSymbolAddress((void**)&kall, g_kall);
    cudaGetSymbolAddress((void**)&vall, g_vall);
    cudaGetSymbolAddress((void**)&q,    g_q);
    cudaGetSymbolAddress((void**)&x,    g_x);
    cudaGetSymbolAddress((void**)&ao,   g_ao);
    cudaGetSymbolAddress((void**)&h,    g_h);
    cudaGetSymbolAddress((void**)&tmp,  g_t);

    // neighbor lists (rebuilt every call: graph replays must be self-contained)
    nbr_init_kernel<<<(NN * KK + 255) / 256, 256>>>();
    nbr_scatter_kernel<<<(EE + 255) / 256, 256>>>(ei);
    nbr_iso_kernel<<<(NN + 255) / 256, 256>>>();

    // K/V projections of spatial_embed for both layers (layer-invariant input)
    for (int l = 0; l < LL; l++) {
        const float* Wk = ipw + ((size_t)l * 3 * DD + DD) * DD;
        const float* Wv = ipw + ((size_t)l * 3 * DD + 2 * DD) * DD;
        const float* bk = ipb + (size_t)l * 3 * DD + DD;
        const float* bv = ipb + (size_t)l * 3 * DD + 2 * DD;
        run_gemm(spatial, Wk, bk, kall + (size_t)l * NN * DD, NN, DD, DD, 0);
        run_gemm(spatial, Wv, bv, vall + (size_t)l * NN * DD, NN, DD, DD, 0);
    }

    for (int l = 0; l < LL; l++) {
        const float* xin = (l == 0) ? expr : x;
        const float* Wq = ipw + (size_t)l * 3 * DD * DD;
        const float* bq = ipb + (size_t)l * 3 * DD;

        run_gemm(xin, Wq, bq, q, NN, DD, DD, 0);

        attn_kernel<<<NN, 128>>>(q, kall + (size_t)l * NN * DD,
                                 vall + (size_t)l * NN * DD, ao);

        run_gemm(ao, opw + (size_t)l * DD * DD, opb + (size_t)l * DD,
                 tmp, NN, DD, DD, 0);

        add_ln_kernel<<<NN, DD>>>(xin, tmp, ln1g + (size_t)l * DD,
                                  ln1b + (size_t)l * DD, x);

        run_gemm(x, w1 + (size_t)l * 2 * DD * DD, b1 + (size_t)l * 2 * DD,
                 h, NN, 2 * DD, DD, 1);
        run_gemm(h, w2 + (size_t)l * DD * 2 * DD, b2 + (size_t)l * DD,
                 tmp, NN, DD, 2 * DD, 0);

        float* xo = (l == LL - 1) ? out : x;
        add_ln_kernel<<<NN, DD>>>(x, tmp, ln2g + (size_t)l * DD,
                                  ln2b + (size_t)l * DD, xo);
    }
}

// round 2
// speedup vs baseline: 1.7242x; 1.7242x over previous
#include <cuda_runtime.h>
#include <math.h>

#define NN 20000
#define DD 256
#define HH 4
#define DHH 64
#define LL 2
#define EE 320000
#define KK 48
#define LN_EPS 1e-5f

// ---------------- scratch (static device globals; no allocation) -------------
__device__ float g_kall[LL][(size_t)NN * DD];
__device__ float g_vall[LL][(size_t)NN * DD];
__device__ float g_q[(size_t)NN * DD];
__device__ float g_x[(size_t)NN * DD];
__device__ float g_ao[(size_t)NN * DD];
__device__ float g_h[(size_t)NN * 2 * DD];
__device__ float g_t[(size_t)NN * DD];
__device__ int   g_counts[NN];
__device__ int   g_nbr[NN * KK];
__device__ int   g_pad[NN * KK];

// ---------------- neighbor build --------------------------------------------
__global__ void nbr_init_kernel() {
    int i = blockIdx.x * blockDim.x + threadIdx.x;
    if (i < NN) g_counts[i] = 0;
    if (i < NN * KK) g_pad[i] = 1;
}

__global__ void nbr_scatter_kernel(const int* __restrict__ ei) {
    int e = blockIdx.x * blockDim.x + threadIdx.x;
    if (e >= EE) return;
    int s = ei[e];
    int t = ei[EE + e];
    int p = atomicAdd(&g_counts[t], 1);
    if (p < KK) {
        g_nbr[t * KK + p] = s;
        g_pad[t * KK + p] = 0;
    }
}

__global__ void nbr_iso_kernel() {
    int n = blockIdx.x * blockDim.x + threadIdx.x;
    if (n < NN && g_counts[n] == 0) {
        g_nbr[n * KK] = n;
        g_pad[n * KK] = 0;
    }
}

// ---------------- tf32 tensor-core GEMM --------------------------------------
// C[M,Nout] = A[M,Kd] @ B[Nout,Kd]^T + bias (+gelu)
// Block tile 128x128, BK=32, 256 threads (8 warps), warp tile 32x64.
// mma.sync.aligned.m16n8k8.row.col.f32.tf32.tf32.f32

__device__ __forceinline__ unsigned f2tf(float x) {
    unsigned r;
    asm("cvt.rna.tf32.f32 %0, %1;" : "=r"(r) : "f"(x));
    return r;
}

#define SMS 36  // smem row stride (floats): (4r+k)%32 unique -> conflict-free frags

__global__ __launch_bounds__(256) void gemm_tf32_kernel(
        const float* __restrict__ A,
        const float* __restrict__ B,
        const float* __restrict__ bias,
        float* __restrict__ C,
        int M, int Nout, int Kd, int act) {
    __shared__ unsigned As[128 * SMS];
    __shared__ unsigned Bs[128 * SMS];

    const int tid  = threadIdx.x;
    const int wid  = tid >> 5;
    const int lane = tid & 31;
    const int g    = lane >> 2;       // group id 0..7
    const int tg   = lane & 3;        // thread-in-group 0..3

    const int warp_m = wid & 3;       // 0..3 -> 32 rows each
    const int warp_n = wid >> 2;      // 0..1 -> 64 cols each

    const int m0 = blockIdx.y * 128;
    const int n0 = blockIdx.x * 128;

    float acc[2][8][4];
#pragma unroll
    for (int i = 0; i < 2; i++)
#pragma unroll
        for (int j = 0; j < 8; j++)
#pragma unroll
            for (int c = 0; c < 4; c++) acc[i][j][c] = 0.0f;

    for (int k0 = 0; k0 < Kd; k0 += 32) {
        // load A tile (128x32) and B tile (128x32), convert to tf32
#pragma unroll
        for (int i = 0; i < 4; i++) {
            int idx  = tid + i * 256;        // float4 index
            int row  = idx >> 3;
            int col  = (idx & 7) * 4;
            int m    = m0 + row;
            float4 va = (m < M) ? *(const float4*)(A + (size_t)m * Kd + k0 + col)
                                : make_float4(0.f, 0.f, 0.f, 0.f);
            unsigned* ap = &As[row * SMS + col];
            ap[0] = f2tf(va.x); ap[1] = f2tf(va.y);
            ap[2] = f2tf(va.z); ap[3] = f2tf(va.w);
            float4 vb = *(const float4*)(B + (size_t)(n0 + row) * Kd + k0 + col);
            unsigned* bp = &Bs[row * SMS + col];
            bp[0] = f2tf(vb.x); bp[1] = f2tf(vb.y);
            bp[2] = f2tf(vb.z); bp[3] = f2tf(vb.w);
        }
        __syncthreads();

#pragma unroll
        for (int ks = 0; ks < 4; ks++) {
            const int kk = ks * 8;
            unsigned a[2][4], b[8][2];
#pragma unroll
            for (int mt = 0; mt < 2; mt++) {
                int r = warp_m * 32 + mt * 16 + g;
                a[mt][0] = As[r * SMS + kk + tg];
                a[mt][1] = As[(r + 8) * SMS + kk + tg];
                a[mt][2] = As[r * SMS + kk + tg + 4];
                a[mt][3] = As[(r + 8) * SMS + kk + tg + 4];
            }
#pragma unroll
            for (int nt = 0; nt < 8; nt++) {
                int nb = warp_n * 64 + nt * 8 + g;
                b[nt][0] = Bs[nb * SMS + kk + tg];
                b[nt][1] = Bs[nb * SMS + kk + tg + 4];
            }
#pragma unroll
            for (int mt = 0; mt < 2; mt++)
#pragma unroll
                for (int nt = 0; nt < 8; nt++) {
                    asm volatile(
                        "mma.sync.aligned.m16n8k8.row.col.f32.tf32.tf32.f32 "
                        "{%0,%1,%2,%3}, {%4,%5,%6,%7}, {%8,%9}, {%0,%1,%2,%3};"
                        : "+f"(acc[mt][nt][0]), "+f"(acc[mt][nt][1]),
                          "+f"(acc[mt][nt][2]), "+f"(acc[mt][nt][3])
                        : "r"(a[mt][0]), "r"(a[mt][1]), "r"(a[mt][2]), "r"(a[mt][3]),
                          "r"(b[nt][0]), "r"(b[nt][1]));
                }
        }
        __syncthreads();
    }

    // epilogue: bias (+gelu), write C
#pragma unroll
    for (int mt = 0; mt < 2; mt++) {
        int r0 = m0 + warp_m * 32 + mt * 16 + g;
        int r1 = r0 + 8;
#pragma unroll
        for (int nt = 0; nt < 8; nt++) {
            int cb = n0 + warp_n * 64 + nt * 8 + tg * 2;
            float bv0 = bias[cb], bv1 = bias[cb + 1];
            float v0 = acc[mt][nt][0] + bv0;
            float v1 = acc[mt][nt][1] + bv1;
            float v2 = acc[mt][nt][2] + bv0;
            float v3 = acc[mt][nt][3] + bv1;
            if (act) {
                v0 = 0.5f * v0 * (1.0f + erff(v0 * 0.70710678f));
                v1 = 0.5f * v1 * (1.0f + erff(v1 * 0.70710678f));
                v2 = 0.5f * v2 * (1.0f + erff(v2 * 0.70710678f));
                v3 = 0.5f * v3 * (1.0f + erff(v3 * 0.70710678f));
            }
            if (r0 < M) *(float2*)(C + (size_t)r0 * Nout + cb) = make_float2(v0, v1);
            if (r1 < M) *(float2*)(C + (size_t)r1 * Nout + cb) = make_float2(v2, v3);
        }
    }
}

// ---------------- attention: one block per node, one warp per head ----------
__global__ void attn_kernel(const float* __restrict__ q,
                            const float* __restrict__ kall,
                            const float* __restrict__ vall,
                            float* __restrict__ ao) {
    int n = blockIdx.x;
    int warp = threadIdx.x >> 5;   // head
    int lane = threadIdx.x & 31;

    __shared__ float s_sc[HH][KK];
    __shared__ int   s_nbr[KK];
    __shared__ int   s_pad[KK];

    for (int j = threadIdx.x; j < KK; j += blockDim.x) {
        s_nbr[j] = g_nbr[n * KK + j];
        s_pad[j] = g_pad[n * KK + j];
    }
    __syncthreads();

    const float2* q2 = (const float2*)(q + (size_t)n * DD + warp * DHH);
    float2 myq = q2[lane];

    for (int j = 0; j < KK; j++) {
        if (s_pad[j]) {
            if (lane == 0) s_sc[warp][j] = -1e30f;
            continue;
        }
        const float2* k2 = (const float2*)(kall + (size_t)s_nbr[j] * DD + warp * DHH);
        float2 kv = k2[lane];
        float dot = myq.x * kv.x + myq.y * kv.y;
#pragma unroll
        for (int o = 16; o; o >>= 1) dot += __shfl_xor_sync(0xffffffffu, dot, o);
        if (lane == 0) s_sc[warp][j] = dot * 0.125f;
    }
    __syncwarp();

    float a0 = s_sc[warp][lane];
    float a1 = (lane < 16) ? s_sc[warp][lane + 32] : -1e30f;
    float mx = fmaxf(a0, a1);
#pragma unroll
    for (int o = 16; o; o >>= 1) mx = fmaxf(mx, __shfl_xor_sync(0xffffffffu, mx, o));
    float e0 = __expf(a0 - mx);
    float e1 = (lane < 16) ? __expf(a1 - mx) : 0.0f;
    float s = e0 + e1;
#pragma unroll
    for (int o = 16; o; o >>= 1) s += __shfl_xor_sync(0xffffffffu, s, o);
    float inv = 1.0f / s;
    s_sc[warp][lane] = e0 * inv;
    if (lane < 16) s_sc[warp][lane + 32] = e1 * inv;
    __syncwarp();

    float2 acc = {0.0f, 0.0f};
    for (int j = 0; j < KK; j++) {
        if (s_pad[j]) continue;
        float w = s_sc[warp][j];
        const float2* v2 = (const float2*)(vall + (size_t)s_nbr[j] * DD + warp * DHH);
        float2 vv = v2[lane];
        acc.x += w * vv.x;
        acc.y += w * vv.y;
    }
    ((float2*)(ao + (size_t)n * DD + warp * DHH))[lane] = acc;
}

// ---------------- residual add + layernorm -----------------------------------
__global__ void add_ln_kernel(const float* __restrict__ x,
                              const float* __restrict__ y,
                              const float* __restrict__ g,
                              const float* __restrict__ b,
                              float* __restrict__ out) {
    int n = blockIdx.x;
    int t = threadIdx.x;
    size_t idx = (size_t)n * DD + t;
    float v = x[idx] + y[idx];

    float s = v, s2 = v * v;
#pragma unroll
    for (int o = 16; o; o >>= 1) {
        s  += __shfl_xor_sync(0xffffffffu, s,  o);
        s2 += __shfl_xor_sync(0xffffffffu, s2, o);
    }
    __shared__ float rs[8], rs2[8];
    if ((t & 31) == 0) { rs[t >> 5] = s; rs2[t >> 5] = s2; }
    __syncthreads();
    float S = 0.0f, S2 = 0.0f;
#pragma unroll
    for (int i = 0; i < 8; i++) { S += rs[i]; S2 += rs2[i]; }
    float mu  = S * (1.0f / DD);
    float var = S2 * (1.0f / DD) - mu * mu;
    out[idx] = (v - mu) * rsqrtf(var + LN_EPS) * g[t] + b[t];
}

// ---------------- launch -----------------------------------------------------
static inline void run_gemm(const float* A, const float* B, const float* bias,
                            float* C, int M, int Nout, int Kd, int act) {
    dim3 grid(Nout / 128, (M + 127) / 128);
    gemm_tf32_kernel<<<grid, 256>>>(A, B, bias, C, M, Nout, Kd, act);
}

extern "C" void kernel_launch(void* const* d_in, const int* in_sizes, int n_in,
                              void* d_out, int out_size) {
    const float* expr    = (const float*)d_in[0];
    const float* spatial = (const float*)d_in[1];
    const float* ipw     = (const float*)d_in[2];
    const float* ipb     = (const float*)d_in[3];
    const float* opw     = (const float*)d_in[4];
    const float* opb     = (const float*)d_in[5];
    const float* w1      = (const float*)d_in[6];
    const float* b1      = (const float*)d_in[7];
    const float* w2      = (const float*)d_in[8];
    const float* b2      = (const float*)d_in[9];
    const float* ln1g    = (const float*)d_in[10];
    const float* ln1b    = (const float*)d_in[11];
    const float* ln2g    = (const float*)d_in[12];
    const float* ln2b    = (const float*)d_in[13];
    const int*   ei      = (const int*)d_in[14];
    float* out = (float*)d_out;

    float *kall, *vall, *q, *x, *ao, *h, *tmp;
    cudaGetSymbolAddress((void**)&kall, g_kall);
    cudaGetSymbolAddress((void**)&vall, g_vall);
    cudaGetSymbolAddress((void**)&q,    g_q);
    cudaGetSymbolAddress((void**)&x,    g_x);
    cudaGetSymbolAddress((void**)&ao,   g_ao);
    cudaGetSymbolAddress((void**)&h,    g_h);
    cudaGetSymbolAddress((void**)&tmp,  g_t);

    nbr_init_kernel<<<(NN * KK + 255) / 256, 256>>>();
    nbr_scatter_kernel<<<(EE + 255) / 256, 256>>>(ei);
    nbr_iso_kernel<<<(NN + 255) / 256, 256>>>();

    for (int l = 0; l < LL; l++) {
        const float* Wk = ipw + ((size_t)l * 3 * DD + DD) * DD;
        const float* Wv = ipw + ((size_t)l * 3 * DD + 2 * DD) * DD;
        const float* bk = ipb + (size_t)l * 3 * DD + DD;
        const float* bv = ipb + (size_t)l * 3 * DD + 2 * DD;
        run_gemm(spatial, Wk, bk, kall + (size_t)l * NN * DD, NN, DD, DD, 0);
        run_gemm(spatial, Wv, bv, vall + (size_t)l * NN * DD, NN, DD, DD, 0);
    }

    for (int l = 0; l < LL; l++) {
        const float* xin = (l == 0) ? expr : x;
        const float* Wq = ipw + (size_t)l * 3 * DD * DD;
        const float* bq = ipb + (size_t)l * 3 * DD;

        run_gemm(xin, Wq, bq, q, NN, DD, DD, 0);

        attn_kernel<<<NN, 128>>>(q, kall + (size_t)l * NN * DD,
                                 vall + (size_t)l * NN * DD, ao);

        run_gemm(ao, opw + (size_t)l * DD * DD, opb + (size_t)l * DD,
                 tmp, NN, DD, DD, 0);

        add_ln_kernel<<<NN, DD>>>(xin, tmp, ln1g + (size_t)l * DD,
                                  ln1b + (size_t)l * DD, x);

        run_gemm(x, w1 + (size_t)l * 2 * DD * DD, b1 + (size_t)l * 2 * DD,
                 h, NN, 2 * DD, DD, 1);
        run_gemm(h, w2 + (size_t)l * DD * 2 * DD, b2 + (size_t)l * DD,
                 tmp, NN, DD, 2 * DD, 0);

        float* xo = (l == LL - 1) ? out : x;
        add_ln_kernel<<<NN, DD>>>(x, tmp, ln2g + (size_t)l * DD,
                                  ln2b + (size_t)l * DD, xo);
    }
}

// round 3
// speedup vs baseline: 2.1348x; 1.2381x over previous
#include <cuda_runtime.h>
#include <math.h>

#define NN 20000
#define DD 256
#define HH 4
#define DHH 64
#define LL 2
#define EE 320000
#define KK 48
#define LN_EPS 1e-5f

// ---------------- scratch (static device globals; no allocation) -------------
__device__ float g_kv[LL][(size_t)NN * 2 * DD];   // per row: K[0:256) V[256:512)
__device__ float g_q[(size_t)NN * DD];
__device__ float g_x[(size_t)NN * DD];
__device__ float g_ao[(size_t)NN * DD];
__device__ float g_h[(size_t)NN * 2 * DD];
__device__ float g_t[(size_t)NN * DD];
__device__ int   g_counts[NN];
__device__ int   g_nbr[NN * KK];
__device__ int   g_pad[NN * KK];

// ---------------- neighbor build --------------------------------------------
__global__ void nbr_init_kernel() {
    int i = blockIdx.x * blockDim.x + threadIdx.x;
    if (i < NN) g_counts[i] = 0;
    if (i < NN * KK) g_pad[i] = 1;
}

__global__ void nbr_scatter_kernel(const int* __restrict__ ei) {
    int e = blockIdx.x * blockDim.x + threadIdx.x;
    if (e >= EE) return;
    int s = ei[e];
    int t = ei[EE + e];
    int p = atomicAdd(&g_counts[t], 1);
    if (p < KK) {
        g_nbr[t * KK + p] = s;
        g_pad[t * KK + p] = 0;
    }
}

__global__ void nbr_iso_kernel() {
    int n = blockIdx.x * blockDim.x + threadIdx.x;
    if (n < NN && g_counts[n] == 0) {
        g_nbr[n * KK] = n;
        g_pad[n * KK] = 0;
    }
}

// ---------------- tf32 tensor-core GEMM, 2-stage pipelined -------------------
// C[M,Nout] = A[M,Kd] @ B[Nout,Kd]^T + bias (+gelu)
// Block tile 128x128, BK=32, 256 threads (8 warps), warp tile 32x64.

__device__ __forceinline__ unsigned f2tf(float x) {
    unsigned r;
    asm("cvt.rna.tf32.f32 %0, %1;" : "=r"(r) : "f"(x));
    return r;
}

#define SMS 36                       // smem row stride (floats), conflict-free
#define STAGE_U (2 * 128 * SMS)      // unsigneds per stage (A tile + B tile)
#define GEMM_SMEM_BYTES (2 * STAGE_U * 4)

__global__ __launch_bounds__(256) void gemm_tf32_kernel(
        const float* __restrict__ A,
        const float* __restrict__ B,
        const float* __restrict__ bias,
        float* __restrict__ C,
        int M, int Nout, int Kd, int act) {
    extern __shared__ unsigned smem[];

    const int tid  = threadIdx.x;
    const int wid  = tid >> 5;
    const int lane = tid & 31;
    const int g    = lane >> 2;
    const int tg   = lane & 3;
    const int warp_m = wid & 3;
    const int warp_n = wid >> 2;
    const int m0 = blockIdx.y * 128;
    const int n0 = blockIdx.x * 128;

    // per-thread load coordinates (fixed across K-tiles)
    const int row_ld = tid >> 3;          // 0..31 (+32*i)
    const int col_ld = (tid & 7) * 4;

    float4 pa[4], pb[4];

    // ---- load tile kt=0 into regs
#pragma unroll
    for (int i = 0; i < 4; i++) {
        int row = row_ld + i * 32;
        int m = m0 + row;
        pa[i] = (m < M) ? *(const float4*)(A + (size_t)m * Kd + col_ld)
                        : make_float4(0.f, 0.f, 0.f, 0.f);
        pb[i] = *(const float4*)(B + (size_t)(n0 + row) * Kd + col_ld);
    }
    // ---- store stage 0
    {
        unsigned* As = smem;
        unsigned* Bs = smem + 128 * SMS;
#pragma unroll
        for (int i = 0; i < 4; i++) {
            int row = row_ld + i * 32;
            unsigned* ap = &As[row * SMS + col_ld];
            ap[0] = f2tf(pa[i].x); ap[1] = f2tf(pa[i].y);
            ap[2] = f2tf(pa[i].z); ap[3] = f2tf(pa[i].w);
            unsigned* bp = &Bs[row * SMS + col_ld];
            bp[0] = f2tf(pb[i].x); bp[1] = f2tf(pb[i].y);
            bp[2] = f2tf(pb[i].z); bp[3] = f2tf(pb[i].w);
        }
    }
    __syncthreads();

    float acc[2][8][4];
#pragma unroll
    for (int i = 0; i < 2; i++)
#pragma unroll
        for (int j = 0; j < 8; j++)
#pragma unroll
            for (int c = 0; c < 4; c++) acc[i][j][c] = 0.0f;

    const int nk = Kd >> 5;
    for (int kt = 0; kt < nk; kt++) {
        const int s = kt & 1;
        // ---- prefetch next K-tile into registers (hidden under the MMAs)
        if (kt + 1 < nk) {
            const int k0 = (kt + 1) * 32;
#pragma unroll
            for (int i = 0; i < 4; i++) {
                int row = row_ld + i * 32;
                int m = m0 + row;
                pa[i] = (m < M) ? *(const float4*)(A + (size_t)m * Kd + k0 + col_ld)
                                : make_float4(0.f, 0.f, 0.f, 0.f);
                pb[i] = *(const float4*)(B + (size_t)(n0 + row) * Kd + k0 + col_ld);
            }
        }

        // ---- compute from stage s
        const unsigned* As = smem + s * STAGE_U;
        const unsigned* Bs = As + 128 * SMS;
#pragma unroll
        for (int ks = 0; ks < 4; ks++) {
            const int kk = ks * 8;
            unsigned a[2][4], b[8][2];
#pragma unroll
            for (int mt = 0; mt < 2; mt++) {
                int r = warp_m * 32 + mt * 16 + g;
                a[mt][0] = As[r * SMS + kk + tg];
                a[mt][1] = As[(r + 8) * SMS + kk + tg];
                a[mt][2] = As[r * SMS + kk + tg + 4];
                a[mt][3] = As[(r + 8) * SMS + kk + tg + 4];
            }
#pragma unroll
            for (int nt = 0; nt < 8; nt++) {
                int nb = warp_n * 64 + nt * 8 + g;
                b[nt][0] = Bs[nb * SMS + kk + tg];
                b[nt][1] = Bs[nb * SMS + kk + tg + 4];
            }
#pragma unroll
            for (int mt = 0; mt < 2; mt++)
#pragma unroll
                for (int nt = 0; nt < 8; nt++) {
                    asm volatile(
                        "mma.sync.aligned.m16n8k8.row.col.f32.tf32.tf32.f32 "
                        "{%0,%1,%2,%3}, {%4,%5,%6,%7}, {%8,%9}, {%0,%1,%2,%3};"
                        : "+f"(acc[mt][nt][0]), "+f"(acc[mt][nt][1]),
                          "+f"(acc[mt][nt][2]), "+f"(acc[mt][nt][3])
                        : "r"(a[mt][0]), "r"(a[mt][1]), "r"(a[mt][2]), "r"(a[mt][3]),
                          "r"(b[nt][0]), "r"(b[nt][1]));
                }
        }

        // ---- store prefetched tile into the other stage
        if (kt + 1 < nk) {
            unsigned* Aw = smem + (s ^ 1) * STAGE_U;
            unsigned* Bw = Aw + 128 * SMS;
#pragma unroll
            for (int i = 0; i < 4; i++) {
                int row = row_ld + i * 32;
                unsigned* ap = &Aw[row * SMS + col_ld];
                ap[0] = f2tf(pa[i].x); ap[1] = f2tf(pa[i].y);
                ap[2] = f2tf(pa[i].z); ap[3] = f2tf(pa[i].w);
                unsigned* bp = &Bw[row * SMS + col_ld];
                bp[0] = f2tf(pb[i].x); bp[1] = f2tf(pb[i].y);
                bp[2] = f2tf(pb[i].z); bp[3] = f2tf(pb[i].w);
            }
            __syncthreads();
        }
    }

    // ---- epilogue: bias (+gelu), write C
#pragma unroll
    for (int mt = 0; mt < 2; mt++) {
        int r0 = m0 + warp_m * 32 + mt * 16 + g;
        int r1 = r0 + 8;
#pragma unroll
        for (int nt = 0; nt < 8; nt++) {
            int cb = n0 + warp_n * 64 + nt * 8 + tg * 2;
            float bv0 = bias[cb], bv1 = bias[cb + 1];
            float v0 = acc[mt][nt][0] + bv0;
            float v1 = acc[mt][nt][1] + bv1;
            float v2 = acc[mt][nt][2] + bv0;
            float v3 = acc[mt][nt][3] + bv1;
            if (act) {
                v0 = 0.5f * v0 * (1.0f + erff(v0 * 0.70710678f));
                v1 = 0.5f * v1 * (1.0f + erff(v1 * 0.70710678f));
                v2 = 0.5f * v2 * (1.0f + erff(v2 * 0.70710678f));
                v3 = 0.5f * v3 * (1.0f + erff(v3 * 0.70710678f));
            }
            if (r0 < M) *(float2*)(C + (size_t)r0 * Nout + cb) = make_float2(v0, v1);
            if (r1 < M) *(float2*)(C + (size_t)r1 * Nout + cb) = make_float2(v2, v3);
        }
    }
}

// ---------------- attention: one block per node, one warp per head ----------
// kv row layout: [K(256) | V(256)], row stride 512
__global__ void attn_kernel(const float* __restrict__ q,
                            const float* __restrict__ kv,
                            float* __restrict__ ao) {
    int n = blockIdx.x;
    int warp = threadIdx.x >> 5;
    int lane = threadIdx.x & 31;

    __shared__ float s_sc[HH][KK];
    __shared__ int   s_nbr[KK];
    __shared__ int   s_pad[KK];

    for (int j = threadIdx.x; j < KK; j += blockDim.x) {
        s_nbr[j] = g_nbr[n * KK + j];
        s_pad[j] = g_pad[n * KK + j];
    }
    __syncthreads();

    const float2* q2 = (const float2*)(q + (size_t)n * DD + warp * DHH);
    float2 myq = q2[lane];

    for (int j = 0; j < KK; j++) {
        if (s_pad[j]) {
            if (lane == 0) s_sc[warp][j] = -1e30f;
            continue;
        }
        const float2* k2 = (const float2*)(kv + (size_t)s_nbr[j] * (2 * DD) + warp * DHH);
        float2 kvv = k2[lane];
        float dot = myq.x * kvv.x + myq.y * kvv.y;
#pragma unroll
        for (int o = 16; o; o >>= 1) dot += __shfl_xor_sync(0xffffffffu, dot, o);
        if (lane == 0) s_sc[warp][j] = dot * 0.125f;
    }
    __syncwarp();

    float a0 = s_sc[warp][lane];
    float a1 = (lane < 16) ? s_sc[warp][lane + 32] : -1e30f;
    float mx = fmaxf(a0, a1);
#pragma unroll
    for (int o = 16; o; o >>= 1) mx = fmaxf(mx, __shfl_xor_sync(0xffffffffu, mx, o));
    float e0 = __expf(a0 - mx);
    float e1 = (lane < 16) ? __expf(a1 - mx) : 0.0f;
    float s = e0 + e1;
#pragma unroll
    for (int o = 16; o; o >>= 1) s += __shfl_xor_sync(0xffffffffu, s, o);
    float inv = 1.0f / s;
    s_sc[warp][lane] = e0 * inv;
    if (lane < 16) s_sc[warp][lane + 32] = e1 * inv;
    __syncwarp();

    float2 acc = {0.0f, 0.0f};
    for (int j = 0; j < KK; j++) {
        if (s_pad[j]) continue;
        float w = s_sc[warp][j];
        const float2* v2 = (const float2*)(kv + (size_t)s_nbr[j] * (2 * DD) + DD + warp * DHH);
        float2 vv = v2[lane];
        acc.x += w * vv.x;
        acc.y += w * vv.y;
    }
    ((float2*)(ao + (size_t)n * DD + warp * DHH))[lane] = acc;
}

// ---------------- residual add + layernorm -----------------------------------
__global__ void add_ln_kernel(const float* __restrict__ x,
                              const float* __restrict__ y,
                              const float* __restrict__ g,
                              const float* __restrict__ b,
                              float* __restrict__ out) {
    int n = blockIdx.x;
    int t = threadIdx.x;
    size_t idx = (size_t)n * DD + t;
    float v = x[idx] + y[idx];

    float s = v, s2 = v * v;
#pragma unroll
    for (int o = 16; o; o >>= 1) {
        s  += __shfl_xor_sync(0xffffffffu, s,  o);
        s2 += __shfl_xor_sync(0xffffffffu, s2, o);
    }
    __shared__ float rs[8], rs2[8];
    if ((t & 31) == 0) { rs[t >> 5] = s; rs2[t >> 5] = s2; }
    __syncthreads();
    float S = 0.0f, S2 = 0.0f;
#pragma unroll
    for (int i = 0; i < 8; i++) { S += rs[i]; S2 += rs2[i]; }
    float mu  = S * (1.0f / DD);
    float var = S2 * (1.0f / DD) - mu * mu;
    out[idx] = (v - mu) * rsqrtf(var + LN_EPS) * g[t] + b[t];
}

// ---------------- launch -----------------------------------------------------
static inline void run_gemm(const float* A, const float* B, const float* bias,
                            float* C, int M, int Nout, int Kd, int act) {
    dim3 grid(Nout / 128, (M + 127) / 128);
    gemm_tf32_kernel<<<grid, 256, GEMM_SMEM_BYTES>>>(A, B, bias, C, M, Nout, Kd, act);
}

extern "C" void kernel_launch(void* const* d_in, const int* in_sizes, int n_in,
                              void* d_out, int out_size) {
    const float* expr    = (const float*)d_in[0];
    const float* spatial = (const float*)d_in[1];
    const float* ipw     = (const float*)d_in[2];
    const float* ipb     = (const float*)d_in[3];
    const float* opw     = (const float*)d_in[4];
    const float* opb     = (const float*)d_in[5];
    const float* w1      = (const float*)d_in[6];
    const float* b1      = (const float*)d_in[7];
    const float* w2      = (const float*)d_in[8];
    const float* b2      = (const float*)d_in[9];
    const float* ln1g    = (const float*)d_in[10];
    const float* ln1b    = (const float*)d_in[11];
    const float* ln2g    = (const float*)d_in[12];
    const float* ln2b    = (const float*)d_in[13];
    const int*   ei      = (const int*)d_in[14];
    float* out = (float*)d_out;

    static int smem_set = 0;
    if (!smem_set) {
        cudaFuncSetAttribute(gemm_tf32_kernel,
                             cudaFuncAttributeMaxDynamicSharedMemorySize,
                             GEMM_SMEM_BYTES);
        smem_set = 1;
    }

    float *kv, *q, *x, *ao, *h, *tmp;
    cudaGetSymbolAddress((void**)&kv,  g_kv);
    cudaGetSymbolAddress((void**)&q,   g_q);
    cudaGetSymbolAddress((void**)&x,   g_x);
    cudaGetSymbolAddress((void**)&ao,  g_ao);
    cudaGetSymbolAddress((void**)&h,   g_h);
    cudaGetSymbolAddress((void**)&tmp, g_t);

    nbr_init_kernel<<<(NN * KK + 255) / 256, 256>>>();
    nbr_scatter_kernel<<<(EE + 255) / 256, 256>>>(ei);
    nbr_iso_kernel<<<(NN + 255) / 256, 256>>>();

    // fused K+V projection: rows [D, 3D) of in_proj are [Wk; Wv] (512 x 256)
    for (int l = 0; l < LL; l++) {
        const float* Wkv = ipw + ((size_t)l * 3 * DD + DD) * DD;
        const float* bkv = ipb + (size_t)l * 3 * DD + DD;
        run_gemm(spatial, Wkv, bkv, kv + (size_t)l * NN * 2 * DD, NN, 2 * DD, DD, 0);
    }

    for (int l = 0; l < LL; l++) {
        const float* xin = (l == 0) ? expr : x;
        const float* Wq = ipw + (size_t)l * 3 * DD * DD;
        const float* bq = ipb + (size_t)l * 3 * DD;

        run_gemm(xin, Wq, bq, q, NN, DD, DD, 0);

        attn_kernel<<<NN, 128>>>(q, kv + (size_t)l * NN * 2 * DD, ao);

        run_gemm(ao, opw + (size_t)l * DD * DD, opb + (size_t)l * DD,
                 tmp, NN, DD, DD, 0);

        add_ln_kernel<<<NN, DD>>>(xin, tmp, ln1g + (size_t)l * DD,
                                  ln1b + (size_t)l * DD, x);

        run_gemm(x, w1 + (size_t)l * 2 * DD * DD, b1 + (size_t)l * 2 * DD,
                 h, NN, 2 * DD, DD, 1);
        run_gemm(h, w2 + (size_t)l * DD * 2 * DD, b2 + (size_t)l * DD,
                 tmp, NN, DD, 2 * DD, 0);

        float* xo = (l == LL - 1) ? out : x;
        add_ln_kernel<<<NN, DD>>>(x, tmp, ln2g + (size_t)l * DD,
                                  ln2b + (size_t)l * DD, xo);
    }
}

// round 5
// speedup vs baseline: 2.1401x; 1.0025x over previous
#include <cuda_runtime.h>
#include <stdint.h>
#include <math.h>

#define NN 20000
#define DD 256
#define HH 4
#define DHH 64
#define LL 2
#define EE 320000
#define KK 48
#define LN_EPS 1e-5f

// ---------------- scratch (static device globals; no allocation) -------------
__device__ float g_kv[LL][(size_t)NN * 2 * DD];   // per row: K[0:256) V[256:512)
__device__ float g_q[(size_t)NN * DD];
__device__ float g_x[(size_t)NN * DD];
__device__ float g_ao[(size_t)NN * DD];
__device__ float g_h[(size_t)NN * 2 * DD];
__device__ float g_t[(size_t)NN * DD];
__device__ int   g_counts[NN];
__device__ int   g_nbr[NN * KK];
__device__ int   g_pad[NN * KK];

// ---------------- neighbor build --------------------------------------------
__global__ void nbr_init_kernel() {
    int i = blockIdx.x * blockDim.x + threadIdx.x;
    if (i < NN) g_counts[i] = 0;
    if (i < NN * KK) g_pad[i] = 1;
}

__global__ void nbr_scatter_kernel(const int* __restrict__ ei) {
    int e = blockIdx.x * blockDim.x + threadIdx.x;
    if (e >= EE) return;
    int s = ei[e];
    int t = ei[EE + e];
    int p = atomicAdd(&g_counts[t], 1);
    if (p < KK) {
        g_nbr[t * KK + p] = s;
        g_pad[t * KK + p] = 0;
    }
}

__global__ void nbr_iso_kernel() {
    int n = blockIdx.x * blockDim.x + threadIdx.x;
    if (n < NN && g_counts[n] == 0) {
        g_nbr[n * KK] = n;
        g_pad[n * KK] = 0;
    }
}

// ---------------- tf32 tensor-core GEMM, 4-stage cp.async pipeline -----------
// C[M,Nout] = A[M,Kd] @ B[Nout,Kd]^T + bias (+gelu)
// Block tile 128x128, BK=32, 256 threads (8 warps), warp tile 32x64.

__device__ __forceinline__ unsigned f2tf(float x) {
    unsigned r;
    asm("cvt.rna.tf32.f32 %0, %1;" : "=r"(r) : "f"(x));
    return r;
}

#define SMS 36                         // smem row stride (floats), conflict-free
#define TILE_F (128 * SMS)
#define STAGE_F (2 * TILE_F)
#define NSTAGE 4
#define GEMM_SMEM_BYTES (NSTAGE * STAGE_F * 4)   // 147456 B

__device__ __forceinline__ uint32_t smem_u32(const void* p) {
    uint32_t a;
    asm("{ .reg .u64 t; cvta.to.shared.u64 t, %1; cvt.u32.u64 %0, t; }"
        : "=r"(a) : "l"(p));
    return a;
}

__global__ __launch_bounds__(256) void gemm_tf32_kernel(
        const float* __restrict__ A,
        const float* __restrict__ B,
        const float* __restrict__ bias,
        float* __restrict__ C,
        int M, int Nout, int Kd, int act) {
    extern __shared__ float smem[];
    const uint32_t smem_base = smem_u32(smem);

    const int tid  = threadIdx.x;
    const int wid  = tid >> 5;
    const int lane = tid & 31;
    const int g    = lane >> 2;
    const int tg   = lane & 3;
    const int warp_m = wid & 3;
    const int warp_n = wid >> 2;
    const int m0 = blockIdx.y * 128;
    const int n0 = blockIdx.x * 128;

    const int row_ld = tid >> 3;          // 0..31 (+32*i)
    const int col_ld = (tid & 7) * 4;

    const int nk = Kd >> 5;

    // issue one stage of async copies (tile kt -> stage s)
    auto load_tile = [&](int kt, int s) {
        const int k0 = kt * 32;
        const uint32_t abase = smem_base + (uint32_t)s * STAGE_F * 4;
        const uint32_t bbase = abase + TILE_F * 4;
#pragma unroll
        for (int i = 0; i < 4; i++) {
            int row = row_ld + i * 32;
            int m = m0 + row;
            uint32_t adst = abase + (uint32_t)(row * SMS + col_ld) * 4;
            const float* asrc = A + (size_t)m * Kd + k0 + col_ld;
            int ab = (m < M) ? 16 : 0;
            asm volatile("cp.async.cg.shared.global [%0], [%1], 16, %2;"
                         :: "r"(adst), "l"(asrc), "r"(ab));
            uint32_t bdst = bbase + (uint32_t)(row * SMS + col_ld) * 4;
            const float* bsrc = B + (size_t)(n0 + row) * Kd + k0 + col_ld;
            asm volatile("cp.async.cg.shared.global [%0], [%1], 16, %2;"
                         :: "r"(bdst), "l"(bsrc), "r"(16));
        }
        asm volatile("cp.async.commit_group;");
    };

    // prologue: fill 3 stages
    load_tile(0, 0);
    if (nk > 1) load_tile(1, 1);
    if (nk > 2) load_tile(2, 2);

    float acc[2][8][4];
#pragma unroll
    for (int i = 0; i < 2; i++)
#pragma unroll
        for (int j = 0; j < 8; j++)
#pragma unroll
            for (int c = 0; c < 4; c++) acc[i][j][c] = 0.0f;

    for (int kt = 0; kt < nk; kt++) {
        const int s = kt & (NSTAGE - 1);
        asm volatile("cp.async.wait_group 2;");
        __syncthreads();

        if (kt + 3 < nk) load_tile(kt + 3, (kt + 3) & (NSTAGE - 1));

        const float* As = smem + (size_t)s * STAGE_F;
        const float* Bs = As + TILE_F;
#pragma unroll
        for (int ks = 0; ks < 4; ks++) {
            const int kk = ks * 8;
            unsigned a[2][4], b[8][2];
#pragma unroll
            for (int mt = 0; mt < 2; mt++) {
                int r = warp_m * 32 + mt * 16 + g;
                a[mt][0] = f2tf(As[r * SMS + kk + tg]);
                a[mt][1] = f2tf(As[(r + 8) * SMS + kk + tg]);
                a[mt][2] = f2tf(As[r * SMS + kk + tg + 4]);
                a[mt][3] = f2tf(As[(r + 8) * SMS + kk + tg + 4]);
            }
#pragma unroll
            for (int nt = 0; nt < 8; nt++) {
                int nb = warp_n * 64 + nt * 8 + g;
                b[nt][0] = f2tf(Bs[nb * SMS + kk + tg]);
                b[nt][1] = f2tf(Bs[nb * SMS + kk + tg + 4]);
            }
#pragma unroll
            for (int mt = 0; mt < 2; mt++)
#pragma unroll
                for (int nt = 0; nt < 8; nt++) {
                    asm volatile(
                        "mma.sync.aligned.m16n8k8.row.col.f32.tf32.tf32.f32 "
                        "{%0,%1,%2,%3}, {%4,%5,%6,%7}, {%8,%9}, {%0,%1,%2,%3};"
                        : "+f"(acc[mt][nt][0]), "+f"(acc[mt][nt][1]),
                          "+f"(acc[mt][nt][2]), "+f"(acc[mt][nt][3])
                        : "r"(a[mt][0]), "r"(a[mt][1]), "r"(a[mt][2]), "r"(a[mt][3]),
                          "r"(b[nt][0]), "r"(b[nt][1]));
                }
        }
        __syncthreads();
    }

    // epilogue: bias (+gelu), write C
#pragma unroll
    for (int mt = 0; mt < 2; mt++) {
        int r0 = m0 + warp_m * 32 + mt * 16 + g;
        int r1 = r0 + 8;
#pragma unroll
        for (int nt = 0; nt < 8; nt++) {
            int cb = n0 + warp_n * 64 + nt * 8 + tg * 2;
            float bv0 = bias[cb], bv1 = bias[cb + 1];
            float v0 = acc[mt][nt][0] + bv0;
            float v1 = acc[mt][nt][1] + bv1;
            float v2 = acc[mt][nt][2] + bv0;
            float v3 = acc[mt][nt][3] + bv1;
            if (act) {
                v0 = 0.5f * v0 * (1.0f + erff(v0 * 0.70710678f));
                v1 = 0.5f * v1 * (1.0f + erff(v1 * 0.70710678f));
                v2 = 0.5f * v2 * (1.0f + erff(v2 * 0.70710678f));
                v3 = 0.5f * v3 * (1.0f + erff(v3 * 0.70710678f));
            }
            if (r0 < M) *(float2*)(C + (size_t)r0 * Nout + cb) = make_float2(v0, v1);
            if (r1 < M) *(float2*)(C + (size_t)r1 * Nout + cb) = make_float2(v2, v3);
        }
    }
}

// ---------------- attention: one block per node, one warp per head ----------
__global__ void attn_kernel(const float* __restrict__ q,
                            const float* __restrict__ kv,
                            float* __restrict__ ao) {
    int n = blockIdx.x;
    int warp = threadIdx.x >> 5;
    int lane = threadIdx.x & 31;

    __shared__ float s_sc[HH][KK];
    __shared__ int   s_nbr[KK];
    __shared__ int   s_pad[KK];

    for (int j = threadIdx.x; j < KK; j += blockDim.x) {
        s_nbr[j] = g_nbr[n * KK + j];
        s_pad[j] = g_pad[n * KK + j];
    }
    __syncthreads();

    const float2* q2 = (const float2*)(q + (size_t)n * DD + warp * DHH);
    float2 myq = q2[lane];

    for (int j = 0; j < KK; j++) {
        if (s_pad[j]) {
            if (lane == 0) s_sc[warp][j] = -1e30f;
            continue;
        }
        const float2* k2 = (const float2*)(kv + (size_t)s_nbr[j] * (2 * DD) + warp * DHH);
        float2 kvv = k2[lane];
        float dot = myq.x * kvv.x + myq.y * kvv.y;
#pragma unroll
        for (int o = 16; o; o >>= 1) dot += __shfl_xor_sync(0xffffffffu, dot, o);
        if (lane == 0) s_sc[warp][j] = dot * 0.125f;
    }
    __syncwarp();

    float a0 = s_sc[warp][lane];
    float a1 = (lane < 16) ? s_sc[warp][lane + 32] : -1e30f;
    float mx = fmaxf(a0, a1);
#pragma unroll
    for (int o = 16; o; o >>= 1) mx = fmaxf(mx, __shfl_xor_sync(0xffffffffu, mx, o));
    float e0 = __expf(a0 - mx);
    float e1 = (lane < 16) ? __expf(a1 - mx) : 0.0f;
    float s = e0 + e1;
#pragma unroll
    for (int o = 16; o; o >>= 1) s += __shfl_xor_sync(0xffffffffu, s, o);
    float inv = 1.0f / s;
    s_sc[warp][lane] = e0 * inv;
    if (lane < 16) s_sc[warp][lane + 32] = e1 * inv;
    __syncwarp();

    float2 acc = {0.0f, 0.0f};
    for (int j = 0; j < KK; j++) {
        if (s_pad[j]) continue;
        float w = s_sc[warp][j];
        const float2* v2 = (const float2*)(kv + (size_t)s_nbr[j] * (2 * DD) + DD + warp * DHH);
        float2 vv = v2[lane];
        acc.x += w * vv.x;
        acc.y += w * vv.y;
    }
    ((float2*)(ao + (size_t)n * DD + warp * DHH))[lane] = acc;
}

// ---------------- residual add + layernorm -----------------------------------
__global__ void add_ln_kernel(const float* __restrict__ x,
                              const float* __restrict__ y,
                              const float* __restrict__ g,
                              const float* __restrict__ b,
                              float* __restrict__ out) {
    int n = blockIdx.x;
    int t = threadIdx.x;
    size_t idx = (size_t)n * DD + t;
    float v = x[idx] + y[idx];

    float s = v, s2 = v * v;
#pragma unroll
    for (int o = 16; o; o >>= 1) {
        s  += __shfl_xor_sync(0xffffffffu, s,  o);
        s2 += __shfl_xor_sync(0xffffffffu, s2, o);
    }
    __shared__ float rs[8], rs2[8];
    if ((t & 31) == 0) { rs[t >> 5] = s; rs2[t >> 5] = s2; }
    __syncthreads();
    float S = 0.0f, S2 = 0.0f;
#pragma unroll
    for (int i = 0; i < 8; i++) { S += rs[i]; S2 += rs2[i]; }
    float mu  = S * (1.0f / DD);
    float var = S2 * (1.0f / DD) - mu * mu;
    out[idx] = (v - mu) * rsqrtf(var + LN_EPS) * g[t] + b[t];
}

// ---------------- launch -----------------------------------------------------
static inline void run_gemm(const float* A, const float* B, const float* bias,
                            float* C, int M, int Nout, int Kd, int act) {
    dim3 grid(Nout / 128, (M + 127) / 128);
    gemm_tf32_kernel<<<grid, 256, GEMM_SMEM_BYTES>>>(A, B, bias, C, M, Nout, Kd, act);
}

extern "C" void kernel_launch(void* const* d_in, const int* in_sizes, int n_in,
                              void* d_out, int out_size) {
    const float* expr    = (const float*)d_in[0];
    const float* spatial = (const float*)d_in[1];
    const float* ipw     = (const float*)d_in[2];
    const float* ipb     = (const float*)d_in[3];
    const float* opw     = (const float*)d_in[4];
    const float* opb     = (const float*)d_in[5];
    const float* w1      = (const float*)d_in[6];
    const float* b1      = (const float*)d_in[7];
    const float* w2      = (const float*)d_in[8];
    const float* b2      = (const float*)d_in[9];
    const float* ln1g    = (const float*)d_in[10];
    const float* ln1b    = (const float*)d_in[11];
    const float* ln2g    = (const float*)d_in[12];
    const float* ln2b    = (const float*)d_in[13];
    const int*   ei      = (const int*)d_in[14];
    float* out = (float*)d_out;

    static int smem_set = 0;
    if (!smem_set) {
        cudaFuncSetAttribute(gemm_tf32_kernel,
                             cudaFuncAttributeMaxDynamicSharedMemorySize,
                             GEMM_SMEM_BYTES);
        smem_set = 1;
    }

    float *kv, *q, *x, *ao, *h, *tmp;
    cudaGetSymbolAddress((void**)&kv,  g_kv);
    cudaGetSymbolAddress((void**)&q,   g_q);
    cudaGetSymbolAddress((void**)&x,   g_x);
    cudaGetSymbolAddress((void**)&ao,  g_ao);
    cudaGetSymbolAddress((void**)&h,   g_h);
    cudaGetSymbolAddress((void**)&tmp, g_t);

    nbr_init_kernel<<<(NN * KK + 255) / 256, 256>>>();
    nbr_scatter_kernel<<<(EE + 255) / 256, 256>>>(ei);
    nbr_iso_kernel<<<(NN + 255) / 256, 256>>>();

    // fused K+V projection: rows [D, 3D) of in_proj are [Wk; Wv] (512 x 256)
    for (int l = 0; l < LL; l++) {
        const float* Wkv = ipw + ((size_t)l * 3 * DD + DD) * DD;
        const float* bkv = ipb + (size_t)l * 3 * DD + DD;
        run_gemm(spatial, Wkv, bkv, kv + (size_t)l * NN * 2 * DD, NN, 2 * DD, DD, 0);
    }

    for (int l = 0; l < LL; l++) {
        const float* xin = (l == 0) ? expr : x;
        const float* Wq = ipw + (size_t)l * 3 * DD * DD;
        const float* bq = ipb + (size_t)l * 3 * DD;

        run_gemm(xin, Wq, bq, q, NN, DD, DD, 0);

        attn_kernel<<<NN, 128>>>(q, kv + (size_t)l * NN * 2 * DD, ao);

        run_gemm(ao, opw + (size_t)l * DD * DD, opb + (size_t)l * DD,
                 tmp, NN, DD, DD, 0);

        add_ln_kernel<<<NN, DD>>>(xin, tmp, ln1g + (size_t)l * DD,
                                  ln1b + (size_t)l * DD, x);

        run_gemm(x, w1 + (size_t)l * 2 * DD * DD, b1 + (size_t)l * 2 * DD,
                 h, NN, 2 * DD, DD, 1);
        run_gemm(h, w2 + (size_t)l * DD * 2 * DD, b2 + (size_t)l * DD,
                 tmp, NN, DD, 2 * DD, 0);

        float* xo = (l == LL - 1) ? out : x;
        add_ln_kernel<<<NN, DD>>>(x, tmp, ln2g + (size_t)l * DD,
                                  ln2b + (size_t)l * DD, xo);
    }
}

// round 6
// speedup vs baseline: 2.3657x; 1.1054x over previous
#include <cuda_runtime.h>
#include <stdint.h>
#include <math.h>

#define NN 20000
#define DD 256
#define HH 4
#define DHH 64
#define LL 2
#define EE 320000
#define KK 48
#define LN_EPS 1e-5f

// ---------------- scratch (static device globals; no allocation) -------------
__device__ float g_kv[LL][(size_t)NN * 2 * DD];   // per row: K[0:256) V[256:512)
__device__ float g_q[(size_t)NN * DD];
__device__ float g_x[(size_t)NN * DD];
__device__ float g_ao[(size_t)NN * DD];
__device__ float g_h[(size_t)NN * 2 * DD];
__device__ float g_t[(size_t)NN * DD];
__device__ int   g_counts[NN];
__device__ int   g_nbr[NN * KK];
__device__ int   g_pad[NN * KK];

// ---------------- neighbor build --------------------------------------------
__global__ void nbr_init_kernel() {
    int i = blockIdx.x * blockDim.x + threadIdx.x;
    if (i < NN) g_counts[i] = 0;
    if (i < NN * KK) g_pad[i] = 1;
}

__global__ void nbr_scatter_kernel(const int* __restrict__ ei) {
    int e = blockIdx.x * blockDim.x + threadIdx.x;
    if (e >= EE) return;
    int s = ei[e];
    int t = ei[EE + e];
    int p = atomicAdd(&g_counts[t], 1);
    if (p < KK) {
        g_nbr[t * KK + p] = s;
        g_pad[t * KK + p] = 0;
    }
}

__global__ void nbr_iso_kernel() {
    int n = blockIdx.x * blockDim.x + threadIdx.x;
    if (n < NN && g_counts[n] == 0) {
        g_nbr[n * KK] = n;
        g_pad[n * KK] = 0;
    }
}

// ---------------- tf32 tensor-core GEMM, 2-stage cp.async, 2 CTAs/SM ---------
// C[M,Nout] = A[M,Kd] @ B[Nout,Kd]^T + bias (+gelu)
// Block tile 128x128, BK=32, 256 threads (8 warps), warp tile 32x64.

__device__ __forceinline__ unsigned f2tf(float x) {
    unsigned r;
    asm("cvt.rna.tf32.f32 %0, %1;" : "=r"(r) : "f"(x));
    return r;
}

#define SMS 36                         // smem row stride (floats), conflict-free
#define TILE_F (128 * SMS)
#define STAGE_F (2 * TILE_F)
#define NSTAGE 2
#define GEMM_SMEM_BYTES (NSTAGE * STAGE_F * 4)   // 73728 B -> 2 CTAs/SM

__device__ __forceinline__ uint32_t smem_u32(const void* p) {
    uint32_t a;
    asm("{ .reg .u64 t; cvta.to.shared.u64 t, %1; cvt.u32.u64 %0, t; }"
        : "=r"(a) : "l"(p));
    return a;
}

__global__ __launch_bounds__(256, 2) void gemm_tf32_kernel(
        const float* __restrict__ A,
        const float* __restrict__ B,
        const float* __restrict__ bias,
        float* __restrict__ C,
        int M, int Nout, int Kd, int act) {
    extern __shared__ float smem[];
    const uint32_t smem_base = smem_u32(smem);

    const int tid  = threadIdx.x;
    const int wid  = tid >> 5;
    const int lane = tid & 31;
    const int g    = lane >> 2;
    const int tg   = lane & 3;
    const int warp_m = wid & 3;
    const int warp_n = wid >> 2;
    const int m0 = blockIdx.y * 128;
    const int n0 = blockIdx.x * 128;

    const int row_ld = tid >> 3;          // 0..31 (+32*i)
    const int col_ld = (tid & 7) * 4;

    const int nk = Kd >> 5;

    // issue one stage of async copies (tile kt -> stage s)
    auto load_tile = [&](int kt, int s) {
        const int k0 = kt * 32;
        const uint32_t abase = smem_base + (uint32_t)s * STAGE_F * 4;
        const uint32_t bbase = abase + TILE_F * 4;
#pragma unroll
        for (int i = 0; i < 4; i++) {
            int row = row_ld + i * 32;
            int m = m0 + row;
            uint32_t adst = abase + (uint32_t)(row * SMS + col_ld) * 4;
            const float* asrc = A + (size_t)m * Kd + k0 + col_ld;
            int ab = (m < M) ? 16 : 0;
            asm volatile("cp.async.cg.shared.global [%0], [%1], 16, %2;"
                         :: "r"(adst), "l"(asrc), "r"(ab));
            uint32_t bdst = bbase + (uint32_t)(row * SMS + col_ld) * 4;
            const float* bsrc = B + (size_t)(n0 + row) * Kd + k0 + col_ld;
            asm volatile("cp.async.cg.shared.global [%0], [%1], 16, %2;"
                         :: "r"(bdst), "l"(bsrc), "r"(16));
        }
        asm volatile("cp.async.commit_group;");
    };

    // prologue: fill both stages
    load_tile(0, 0);
    if (nk > 1) load_tile(1, 1);

    float acc[2][8][4];
#pragma unroll
    for (int i = 0; i < 2; i++)
#pragma unroll
        for (int j = 0; j < 8; j++)
#pragma unroll
            for (int c = 0; c < 4; c++) acc[i][j][c] = 0.0f;

    for (int kt = 0; kt < nk; kt++) {
        const int s = kt & 1;
        asm volatile("cp.async.wait_group 1;");
        __syncthreads();

        const float* As = smem + (size_t)s * STAGE_F;
        const float* Bs = As + TILE_F;
#pragma unroll
        for (int ks = 0; ks < 4; ks++) {
            const int kk = ks * 8;
            unsigned a[2][4], b[8][2];
#pragma unroll
            for (int mt = 0; mt < 2; mt++) {
                int r = warp_m * 32 + mt * 16 + g;
                a[mt][0] = f2tf(As[r * SMS + kk + tg]);
                a[mt][1] = f2tf(As[(r + 8) * SMS + kk + tg]);
                a[mt][2] = f2tf(As[r * SMS + kk + tg + 4]);
                a[mt][3] = f2tf(As[(r + 8) * SMS + kk + tg + 4]);
            }
#pragma unroll
            for (int nt = 0; nt < 8; nt++) {
                int nb = warp_n * 64 + nt * 8 + g;
                b[nt][0] = f2tf(Bs[nb * SMS + kk + tg]);
                b[nt][1] = f2tf(Bs[nb * SMS + kk + tg + 4]);
            }
#pragma unroll
            for (int mt = 0; mt < 2; mt++)
#pragma unroll
                for (int nt = 0; nt < 8; nt++) {
                    asm volatile(
                        "mma.sync.aligned.m16n8k8.row.col.f32.tf32.tf32.f32 "
                        "{%0,%1,%2,%3}, {%4,%5,%6,%7}, {%8,%9}, {%0,%1,%2,%3};"
                        : "+f"(acc[mt][nt][0]), "+f"(acc[mt][nt][1]),
                          "+f"(acc[mt][nt][2]), "+f"(acc[mt][nt][3])
                        : "r"(a[mt][0]), "r"(a[mt][1]), "r"(a[mt][2]), "r"(a[mt][3]),
                          "r"(b[nt][0]), "r"(b[nt][1]));
                }
        }
        __syncthreads();   // all warps done reading stage s before overwriting it

        if (kt + 2 < nk) load_tile(kt + 2, s);
    }

    // epilogue: bias (+gelu), write C
#pragma unroll
    for (int mt = 0; mt < 2; mt++) {
        int r0 = m0 + warp_m * 32 + mt * 16 + g;
        int r1 = r0 + 8;
#pragma unroll
        for (int nt = 0; nt < 8; nt++) {
            int cb = n0 + warp_n * 64 + nt * 8 + tg * 2;
            float bv0 = bias[cb], bv1 = bias[cb + 1];
            float v0 = acc[mt][nt][0] + bv0;
            float v1 = acc[mt][nt][1] + bv1;
            float v2 = acc[mt][nt][2] + bv0;
            float v3 = acc[mt][nt][3] + bv1;
            if (act) {
                v0 = 0.5f * v0 * (1.0f + erff(v0 * 0.70710678f));
                v1 = 0.5f * v1 * (1.0f + erff(v1 * 0.70710678f));
                v2 = 0.5f * v2 * (1.0f + erff(v2 * 0.70710678f));
                v3 = 0.5f * v3 * (1.0f + erff(v3 * 0.70710678f));
            }
            if (r0 < M) *(float2*)(C + (size_t)r0 * Nout + cb) = make_float2(v0, v1);
            if (r1 < M) *(float2*)(C + (size_t)r1 * Nout + cb) = make_float2(v2, v3);
        }
    }
}

// ---------------- attention: one block per node, one warp per head ----------
__global__ void attn_kernel(const float* __restrict__ q,
                            const float* __restrict__ kv,
                            float* __restrict__ ao) {
    int n = blockIdx.x;
    int warp = threadIdx.x >> 5;
    int lane = threadIdx.x & 31;

    __shared__ float s_sc[HH][KK];
    __shared__ int   s_nbr[KK];
    __shared__ int   s_pad[KK];

    for (int j = threadIdx.x; j < KK; j += blockDim.x) {
        s_nbr[j] = g_nbr[n * KK + j];
        s_pad[j] = g_pad[n * KK + j];
    }
    __syncthreads();

    const float2* q2 = (const float2*)(q + (size_t)n * DD + warp * DHH);
    float2 myq = q2[lane];

    for (int j = 0; j < KK; j++) {
        if (s_pad[j]) {
            if (lane == 0) s_sc[warp][j] = -1e30f;
            continue;
        }
        const float2* k2 = (const float2*)(kv + (size_t)s_nbr[j] * (2 * DD) + warp * DHH);
        float2 kvv = k2[lane];
        float dot = myq.x * kvv.x + myq.y * kvv.y;
#pragma unroll
        for (int o = 16; o; o >>= 1) dot += __shfl_xor_sync(0xffffffffu, dot, o);
        if (lane == 0) s_sc[warp][j] = dot * 0.125f;
    }
    __syncwarp();

    float a0 = s_sc[warp][lane];
    float a1 = (lane < 16) ? s_sc[warp][lane + 32] : -1e30f;
    float mx = fmaxf(a0, a1);
#pragma unroll
    for (int o = 16; o; o >>= 1) mx = fmaxf(mx, __shfl_xor_sync(0xffffffffu, mx, o));
    float e0 = __expf(a0 - mx);
    float e1 = (lane < 16) ? __expf(a1 - mx) : 0.0f;
    float s = e0 + e1;
#pragma unroll
    for (int o = 16; o; o >>= 1) s += __shfl_xor_sync(0xffffffffu, s, o);
    float inv = 1.0f / s;
    s_sc[warp][lane] = e0 * inv;
    if (lane < 16) s_sc[warp][lane + 32] = e1 * inv;
    __syncwarp();

    float2 acc = {0.0f, 0.0f};
    for (int j = 0; j < KK; j++) {
        if (s_pad[j]) continue;
        float w = s_sc[warp][j];
        const float2* v2 = (const float2*)(kv + (size_t)s_nbr[j] * (2 * DD) + DD + warp * DHH);
        float2 vv = v2[lane];
        acc.x += w * vv.x;
        acc.y += w * vv.y;
    }
    ((float2*)(ao + (size_t)n * DD + warp * DHH))[lane] = acc;
}

// ---------------- residual add + layernorm -----------------------------------
__global__ void add_ln_kernel(const float* __restrict__ x,
                              const float* __restrict__ y,
                              const float* __restrict__ g,
                              const float* __restrict__ b,
                              float* __restrict__ out) {
    int n = blockIdx.x;
    int t = threadIdx.x;
    size_t idx = (size_t)n * DD + t;
    float v = x[idx] + y[idx];

    float s = v, s2 = v * v;
#pragma unroll
    for (int o = 16; o; o >>= 1) {
        s  += __shfl_xor_sync(0xffffffffu, s,  o);
        s2 += __shfl_xor_sync(0xffffffffu, s2, o);
    }
    __shared__ float rs[8], rs2[8];
    if ((t & 31) == 0) { rs[t >> 5] = s; rs2[t >> 5] = s2; }
    __syncthreads();
    float S = 0.0f, S2 = 0.0f;
#pragma unroll
    for (int i = 0; i < 8; i++) { S += rs[i]; S2 += rs2[i]; }
    float mu  = S * (1.0f / DD);
    float var = S2 * (1.0f / DD) - mu * mu;
    out[idx] = (v - mu) * rsqrtf(var + LN_EPS) * g[t] + b[t];
}

// ---------------- launch -----------------------------------------------------
static inline void run_gemm(const float* A, const float* B, const float* bias,
                            float* C, int M, int Nout, int Kd, int act) {
    dim3 grid(Nout / 128, (M + 127) / 128);
    gemm_tf32_kernel<<<grid, 256, GEMM_SMEM_BYTES>>>(A, B, bias, C, M, Nout, Kd, act);
}

extern "C" void kernel_launch(void* const* d_in, const int* in_sizes, int n_in,
                              void* d_out, int out_size) {
    const float* expr    = (const float*)d_in[0];
    const float* spatial = (const float*)d_in[1];
    const float* ipw     = (const float*)d_in[2];
    const float* ipb     = (const float*)d_in[3];
    const float* opw     = (const float*)d_in[4];
    const float* opb     = (const float*)d_in[5];
    const float* w1      = (const float*)d_in[6];
    const float* b1      = (const float*)d_in[7];
    const float* w2      = (const float*)d_in[8];
    const float* b2      = (const float*)d_in[9];
    const float* ln1g    = (const float*)d_in[10];
    const float* ln1b    = (const float*)d_in[11];
    const float* ln2g    = (const float*)d_in[12];
    const float* ln2b    = (const float*)d_in[13];
    const int*   ei      = (const int*)d_in[14];
    float* out = (float*)d_out;

    static int smem_set = 0;
    if (!smem_set) {
        cudaFuncSetAttribute(gemm_tf32_kernel,
                             cudaFuncAttributeMaxDynamicSharedMemorySize,
                             GEMM_SMEM_BYTES);
        smem_set = 1;
    }

    float *kv, *q, *x, *ao, *h, *tmp;
    cudaGetSymbolAddress((void**)&kv,  g_kv);
    cudaGetSymbolAddress((void**)&q,   g_q);
    cudaGetSymbolAddress((void**)&x,   g_x);
    cudaGetSymbolAddress((void**)&ao,  g_ao);
    cudaGetSymbolAddress((void**)&h,   g_h);
    cudaGetSymbolAddress((void**)&tmp, g_t);

    nbr_init_kernel<<<(NN * KK + 255) / 256, 256>>>();
    nbr_scatter_kernel<<<(EE + 255) / 256, 256>>>(ei);
    nbr_iso_kernel<<<(NN + 255) / 256, 256>>>();

    // fused K+V projection: rows [D, 3D) of in_proj are [Wk; Wv] (512 x 256)
    for (int l = 0; l < LL; l++) {
        const float* Wkv = ipw + ((size_t)l * 3 * DD + DD) * DD;
        const float* bkv = ipb + (size_t)l * 3 * DD + DD;
        run_gemm(spatial, Wkv, bkv, kv + (size_t)l * NN * 2 * DD, NN, 2 * DD, DD, 0);
    }

    for (int l = 0; l < LL; l++) {
        const float* xin = (l == 0) ? expr : x;
        const float* Wq = ipw + (size_t)l * 3 * DD * DD;
        const float* bq = ipb + (size_t)l * 3 * DD;

        run_gemm(xin, Wq, bq, q, NN, DD, DD, 0);

        attn_kernel<<<NN, 128>>>(q, kv + (size_t)l * NN * 2 * DD, ao);

        run_gemm(ao, opw + (size_t)l * DD * DD, opb + (size_t)l * DD,
                 tmp, NN, DD, DD, 0);

        add_ln_kernel<<<NN, DD>>>(xin, tmp, ln1g + (size_t)l * DD,
                                  ln1b + (size_t)l * DD, x);

        run_gemm(x, w1 + (size_t)l * 2 * DD * DD, b1 + (size_t)l * 2 * DD,
                 h, NN, 2 * DD, DD, 1);
        run_gemm(h, w2 + (size_t)l * DD * 2 * DD, b2 + (size_t)l * DD,
                 tmp, NN, DD, 2 * DD, 0);

        float* xo = (l == LL - 1) ? out : x;
        add_ln_kernel<<<NN, DD>>>(x, tmp, ln2g + (size_t)l * DD,
                                  ln2b + (size_t)l * DD, xo);
    }
}